// round 1
// baseline (speedup 1.0000x reference)
#include <cuda_runtime.h>

// SwitchingLinear: out[b, :] = W[idx[b]] @ x[b]
// B=2048, C=64, IN=512, OUT=512, all fp32 (index int64-or-int32, detected).
//
// Strategy: counting-sort samples by expert (4 tiny kernels), then grouped
// GEMM: one CTA per (row-tile slot, N-tile). Weights stay hot in L2 (64MB).

#define BB    2048
#define CC    64
#define KIN   512
#define NOUT  512
#define TM    32
#define TN    128
#define BK    32
#define MAXTILES 160   // worst-case sum ceil(cnt/TM) <= 126

__device__ int g_count[CC];
__device__ int g_cursor[CC];
__device__ int g_offset[CC + 1];
__device__ int g_sorted[BB];
__device__ int g_tile_e[MAXTILES];
__device__ int g_tile_r[MAXTILES];
__device__ int g_ntiles;
__device__ int g_is64;

// Zero histograms + detect index dtype (int64 little-endian => odd 32-bit
// words of the first 128 elements are all zero; values are in [0,64)).
__global__ void k_init(const int* __restrict__ idx32) {
    int t = threadIdx.x;
    if (t < CC) { g_count[t] = 0; g_cursor[t] = 0; }
    if (t == 0) {
        int any = 0;
#pragma unroll 8
        for (int i = 1; i < 256; i += 2) any |= idx32[i];
        g_is64 = (any == 0) ? 1 : 0;
    }
}

__global__ void k_hist(const int* __restrict__ idx) {
    __shared__ int h[CC];
    int t = threadIdx.x;
    if (t < CC) h[t] = 0;
    __syncthreads();
    int b = blockIdx.x * blockDim.x + t;
    if (b < BB) {
        int c = g_is64 ? idx[2 * b] : idx[b];
        atomicAdd(&h[c], 1);
    }
    __syncthreads();
    if (t < CC && h[t]) atomicAdd(&g_count[t], h[t]);
}

__global__ void k_scan() {
    __shared__ int sc[CC];
    int t = threadIdx.x;
    if (t < CC) sc[t] = g_count[t];
    __syncthreads();
    if (t == 0) {
        int off = 0, nt = 0;
        for (int e = 0; e < CC; e++) {
            g_offset[e] = off;
            int cnt = sc[e];
            for (int r = 0; r < cnt; r += TM) {
                g_tile_e[nt] = e;
                g_tile_r[nt] = r;
                nt++;
            }
            off += cnt;
        }
        g_offset[CC] = off;
        g_ntiles = nt;
    }
}

__global__ void k_scatter(const int* __restrict__ idx) {
    int b = blockIdx.x * blockDim.x + threadIdx.x;
    if (b < BB) {
        int c = g_is64 ? idx[2 * b] : idx[b];
        int p = atomicAdd(&g_cursor[c], 1);
        g_sorted[g_offset[c] + p] = b;
    }
}

// Grouped GEMM. CTA = (slot in tile table, N-tile). 256 threads.
// Thread computes a 4x4 micro-tile of the 32x128 C tile.
// Smem layouts are k-major with XOR swizzle (m^4s / n^4s, s=(k>>2)&7):
// all STS conflict-free, A compute-reads broadcast, B compute-reads full-row.
__global__ __launch_bounds__(256, 2)
void k_gemm(const float* __restrict__ x, const float* __restrict__ w,
            float* __restrict__ out) {
    int slot = blockIdx.x;
    if (slot >= g_ntiles) return;
    int e    = g_tile_e[slot];
    int row0 = g_offset[e] + g_tile_r[slot];
    int m_cnt = g_offset[e + 1] - row0;
    if (m_cnt > TM) m_cnt = TM;
    int n0 = blockIdx.y * TN;

    __shared__ float As[BK][TM];
    __shared__ float Bs[BK][TN];
    __shared__ int   sid[TM];

    int t = threadIdx.x;
    if (t < TM) sid[t] = (t < m_cnt) ? g_sorted[row0 + t] : -1;
    __syncthreads();

    const float* wc = w + (size_t)e * (NOUT * KIN) + (size_t)n0 * KIN;

    // Load mapping: 8 lanes per row, float4 along k.
    int a_row = t >> 3;          // 0..31 (A: sample row; B: n-row base)
    int a_k   = (t & 7) << 2;    // 0,4,...,28
    int sw    = a_k;             // 4*((a_k>>2)&7) == a_k here

    int r = sid[a_row];
    const float* ap = x + (size_t)(r < 0 ? 0 : r) * KIN + a_k;
    const float* bp = wc + (size_t)a_row * KIN + a_k;

    // Prefetch k0 = 0 into registers.
    float4 avr = (r >= 0) ? *(const float4*)ap : make_float4(0.f, 0.f, 0.f, 0.f);
    float4 bvr[4];
#pragma unroll
    for (int q = 0; q < 4; q++)
        bvr[q] = *(const float4*)(bp + (size_t)q * 32 * KIN);

    int tmb = (t >> 5) << 2;     // micro-tile m base (const per warp)
    int tnb = (t & 31) << 2;     // micro-tile n base

    float acc[4][4] = {};

    for (int k0 = 0; k0 < KIN; k0 += BK) {
        // Store prefetched tile to smem (swizzled, conflict-free).
        {
            int mi = a_row ^ sw;
            As[a_k + 0][mi] = avr.x;
            As[a_k + 1][mi] = avr.y;
            As[a_k + 2][mi] = avr.z;
            As[a_k + 3][mi] = avr.w;
#pragma unroll
            for (int q = 0; q < 4; q++) {
                int ni = (a_row + 32 * q) ^ sw;
                Bs[a_k + 0][ni] = bvr[q].x;
                Bs[a_k + 1][ni] = bvr[q].y;
                Bs[a_k + 2][ni] = bvr[q].z;
                Bs[a_k + 3][ni] = bvr[q].w;
            }
        }
        __syncthreads();

        // Prefetch next K-tile while computing this one.
        if (k0 + BK < KIN) {
            avr = (r >= 0) ? *(const float4*)(ap + k0 + BK)
                           : make_float4(0.f, 0.f, 0.f, 0.f);
#pragma unroll
            for (int q = 0; q < 4; q++)
                bvr[q] = *(const float4*)(bp + (size_t)q * 32 * KIN + k0 + BK);
        }

#pragma unroll
        for (int kk = 0; kk < BK; kk++) {
            int s2 = kk & 28;   // 4*((kk>>2)&7)
            float4 a = *(const float4*)&As[kk][tmb ^ s2];
            float4 b = *(const float4*)&Bs[kk][tnb ^ s2];
            acc[0][0] += a.x * b.x; acc[0][1] += a.x * b.y;
            acc[0][2] += a.x * b.z; acc[0][3] += a.x * b.w;
            acc[1][0] += a.y * b.x; acc[1][1] += a.y * b.y;
            acc[1][2] += a.y * b.z; acc[1][3] += a.y * b.w;
            acc[2][0] += a.z * b.x; acc[2][1] += a.z * b.y;
            acc[2][2] += a.z * b.z; acc[2][3] += a.z * b.w;
            acc[3][0] += a.w * b.x; acc[3][1] += a.w * b.y;
            acc[3][2] += a.w * b.z; acc[3][3] += a.w * b.w;
        }
        __syncthreads();
    }

    // Epilogue: scatter rows back to their sample positions.
#pragma unroll
    for (int mm = 0; mm < 4; mm++) {
        int rr = sid[tmb + mm];
        if (rr >= 0) {
            float4 v = make_float4(acc[mm][0], acc[mm][1], acc[mm][2], acc[mm][3]);
            *(float4*)(out + (size_t)rr * NOUT + n0 + tnb) = v;
        }
    }
}

extern "C" void kernel_launch(void* const* d_in, const int* in_sizes, int n_in,
                              void* d_out, int out_size) {
    const float* x   = nullptr;
    const int*   idx = nullptr;
    const float* w   = nullptr;
    for (int i = 0; i < n_in; i++) {
        if (in_sizes[i] == BB)                x ? (void)0 : (void)0, idx = (const int*)d_in[i];
        else if (in_sizes[i] == BB * KIN)     x = (const float*)d_in[i];
        else                                   w = (const float*)d_in[i];
    }

    k_init<<<1, 64>>>(idx);
    k_hist<<<(BB + 255) / 256, 256>>>(idx);
    k_scan<<<1, 64>>>();
    k_scatter<<<(BB + 255) / 256, 256>>>(idx);

    dim3 grid(128, NOUT / TN);   // 128 >= max row-tile slots (<=126)
    k_gemm<<<grid, 256>>>(x, w, (float*)d_out);
}

// round 3
// speedup vs baseline: 1.7518x; 1.7518x over previous
#include <cuda_runtime.h>
#include <cuda_bf16.h>
#include <cstdint>

// SwitchingLinear: out[b,:] = W[idx[b]] @ x[b]
// B=2048, C=64, IN=OUT=512 fp32.
// Split-bf16 HMMA (mma.sync.m16n8k16) grouped GEMM:
//   v = hi(bf16) + lo(bf16);  D = Ah*Bh + Ah*Bl + Al*Bh  (fp32 accum)
// CTA = (expert tile TM=64 padded, N-block 128). K in 32-chunks,
// double-buffered static smem (48KB), SW64 swizzle, reg-prefetch pipeline.

#define BB    2048
#define CC    64
#define KIN   512
#define NOUT  512
#define TM    64
#define TN    128
#define KB    32
#define NCH   (KIN / KB)       // 16
#define MAXT  96

__device__ int g_offset[CC + 1];
__device__ int g_sorted[BB];
__device__ int g_tile_e[MAXT];
__device__ int g_tile_r[MAXT];
__device__ int g_ntiles;

__device__ __forceinline__ uint32_t smem_u32(const void* p) {
    uint32_t a;
    asm("{ .reg .u64 t; cvta.to.shared.u64 t, %1; cvt.u32.u64 %0, t; }"
        : "=r"(a) : "l"(p));
    return a;
}

#define SW64(o) ((o) ^ (((o) >> 3) & 0x30))

#define LDSM4(r0, r1, r2, r3, a)                                             \
    asm volatile("ldmatrix.sync.aligned.m8n8.x4.shared.b16 {%0,%1,%2,%3}, [%4];" \
                 : "=r"(r0), "=r"(r1), "=r"(r2), "=r"(r3) : "r"(a))

#define MMA(d, a, b0, b1)                                                    \
    asm volatile("mma.sync.aligned.m16n8k16.row.col.f32.bf16.bf16.f32 "      \
                 "{%0,%1,%2,%3},{%4,%5,%6,%7},{%8,%9},{%0,%1,%2,%3};"        \
                 : "+f"((d)[0]), "+f"((d)[1]), "+f"((d)[2]), "+f"((d)[3])    \
                 : "r"((a)[0]), "r"((a)[1]), "r"((a)[2]), "r"((a)[3]),       \
                   "r"(b0), "r"(b1))

// Split fp32 pair -> bf16x2 hi + bf16x2 lo (lo = v - float(hi)).
__device__ __forceinline__ void cvt2(float f0, float f1, uint32_t& h, uint32_t& l) {
    asm("cvt.rn.bf16x2.f32 %0, %1, %2;" : "=r"(h) : "f"(f1), "f"(f0));
    float h0 = __uint_as_float(h << 16);
    float h1 = __uint_as_float(h & 0xFFFF0000u);
    float l0 = f0 - h0, l1 = f1 - h1;
    asm("cvt.rn.bf16x2.f32 %0, %1, %2;" : "=r"(l) : "f"(l1), "f"(l0));
}

// ---- setup: dtype detect, histogram, scan, tile table, stable scatter ----
__global__ void k_setup(const int* __restrict__ idx) {
    __shared__ int h[CC], cur[CC], off[CC + 1];
    __shared__ int s_is64;
    int t = threadIdx.x;
    if (t == 0) {
        int any = 0;
#pragma unroll 8
        for (int i = 1; i < 256; i += 2) any |= idx[i];
        s_is64 = (any == 0) ? 1 : 0;
    }
    if (t < CC) { h[t] = 0; cur[t] = 0; }
    __syncthreads();
    int is64 = s_is64;
    int b0 = t, b1 = t + 1024;
    int c0 = is64 ? idx[2 * b0] : idx[b0];
    int c1 = is64 ? idx[2 * b1] : idx[b1];
    atomicAdd(&h[c0], 1);
    atomicAdd(&h[c1], 1);
    __syncthreads();
    if (t == 0) {
        int o = 0, nt = 0;
        for (int e = 0; e < CC; e++) {
            off[e] = o;
            int cnt = h[e];
            for (int r = 0; r < cnt; r += TM) { g_tile_e[nt] = e; g_tile_r[nt] = r; nt++; }
            o += cnt;
        }
        off[CC] = o;
        g_ntiles = nt;
    }
    __syncthreads();
    if (t <= CC) g_offset[t] = off[t];
    int p0 = atomicAdd(&cur[c0], 1);
    g_sorted[off[c0] + p0] = b0;
    int p1 = atomicAdd(&cur[c1], 1);
    g_sorted[off[c1] + p1] = b1;
}

// ---- grouped GEMM ----
// smem stage (24KB): Ah[64x64B] | Al | Bh[128x64B] | Bl ; two stages = 48KB.
__global__ __launch_bounds__(256, 2)
void k_gemm(const float* __restrict__ x, const float* __restrict__ w,
            float* __restrict__ out) {
    int slot = blockIdx.x;
    if (slot >= g_ntiles) return;

    __shared__ __align__(1024) char sm[49152];
    const uint32_t sb = smem_u32(sm);

    int t = threadIdx.x, wid = t >> 5, lane = t & 31;
    int e    = g_tile_e[slot];
    int row0 = g_offset[e] + g_tile_r[slot];
    int mcnt = g_offset[e + 1] - row0;
    if (mcnt > TM) mcnt = TM;
    int n0 = blockIdx.y * TN;

    const float* wc = w + (size_t)e * (NOUT * KIN) + (size_t)n0 * KIN;

    // Loader mapping: 4 threads/row, 8 floats each.
    int lrow = t >> 2;                 // 0..63
    int kf   = (t & 3) * 8;            // float offset in 32-chunk? no: 0..24
    // NOTE: chunk has 32 floats/row; 4 thr x 8 floats = 32. kf in {0,8,16,24}.
    int asrc = (lrow < mcnt) ? g_sorted[row0 + lrow] : -1;
    const float* ap  = x  + (size_t)(asrc < 0 ? 0 : asrc) * KIN + kf;
    const float* bp0 = wc + (size_t)lrow * KIN + kf;
    const float* bp1 = bp0 + (size_t)64 * KIN;

    // Prefetch chunk 0.
    float4 av[2], bv[4];
    {
        if (asrc >= 0) { av[0] = *(const float4*)ap; av[1] = *(const float4*)(ap + 4); }
        else { av[0] = make_float4(0.f, 0.f, 0.f, 0.f); av[1] = av[0]; }
        bv[0] = *(const float4*)bp0; bv[1] = *(const float4*)(bp0 + 4);
        bv[2] = *(const float4*)bp1; bv[3] = *(const float4*)(bp1 + 4);
    }

    // MMA geometry: warp tile 32x32 at (mbase, nbase).
    int mbase = (wid & 1) * 32;
    int nbase = (wid >> 1) * 32;
    // ldmatrix logical offsets
    int a_r = (lane & 7) + ((lane >> 3) & 1) * 8;   // + mbase + mf*16
    int a_c = ((lane >> 4) & 1) * 16;               // + ks*32
    int b_r = (lane & 7) + ((lane >> 4) & 1) * 8;   // + nbase + nfp*16
    int b_c = ((lane >> 3) & 1) * 16;               // + ks*32

    float acc[2][4][4];
#pragma unroll
    for (int i = 0; i < 2; i++)
#pragma unroll
        for (int j = 0; j < 4; j++)
#pragma unroll
            for (int q = 0; q < 4; q++) acc[i][j][q] = 0.f;

    uint32_t sts_a = SW64((uint32_t)(lrow * 64 + (t & 3) * 16));
    uint32_t sts_b = sts_a;   // same row/col mapping, different base

#pragma unroll 1
    for (int s = 0; s < NCH; s++) {
        char* stg = sm + (s & 1) * 24576;
        // Convert + store prefetched chunk.
        {
            uint32_t h0, l0, h1, l1;
            cvt2(av[0].x, av[0].y, h0, l0); cvt2(av[0].z, av[0].w, h1, l1);
            uint32_t h2, l2, h3, l3;
            cvt2(av[1].x, av[1].y, h2, l2); cvt2(av[1].z, av[1].w, h3, l3);
            *(uint4*)(stg + sts_a)        = make_uint4(h0, h1, h2, h3);
            *(uint4*)(stg + 4096 + sts_a) = make_uint4(l0, l1, l2, l3);
            cvt2(bv[0].x, bv[0].y, h0, l0); cvt2(bv[0].z, bv[0].w, h1, l1);
            cvt2(bv[1].x, bv[1].y, h2, l2); cvt2(bv[1].z, bv[1].w, h3, l3);
            *(uint4*)(stg + 8192 + sts_b)  = make_uint4(h0, h1, h2, h3);
            *(uint4*)(stg + 16384 + sts_b) = make_uint4(l0, l1, l2, l3);
            cvt2(bv[2].x, bv[2].y, h0, l0); cvt2(bv[2].z, bv[2].w, h1, l1);
            cvt2(bv[3].x, bv[3].y, h2, l2); cvt2(bv[3].z, bv[3].w, h3, l3);
            uint32_t o2 = SW64((uint32_t)((lrow + 64) * 64 + (t & 3) * 16));
            *(uint4*)(stg + 8192 + o2)  = make_uint4(h0, h1, h2, h3);
            *(uint4*)(stg + 16384 + o2) = make_uint4(l0, l1, l2, l3);
        }
        __syncthreads();

        // Prefetch next chunk (hidden under MMAs below).
        if (s + 1 < NCH) {
            int g = (s + 1) * KB;
            if (asrc >= 0) {
                av[0] = *(const float4*)(ap + g);
                av[1] = *(const float4*)(ap + g + 4);
            }
            bv[0] = *(const float4*)(bp0 + g); bv[1] = *(const float4*)(bp0 + g + 4);
            bv[2] = *(const float4*)(bp1 + g); bv[3] = *(const float4*)(bp1 + g + 4);
        }

        uint32_t base = sb + (uint32_t)((s & 1) * 24576);
#pragma unroll
        for (int ks = 0; ks < 2; ks++) {
            uint32_t ah[2][4], al[2][4], bh[2][4], bl[2][4];
#pragma unroll
            for (int mf = 0; mf < 2; mf++) {
                uint32_t o = SW64((uint32_t)((mbase + mf * 16 + a_r) * 64 + ks * 32 + a_c));
                LDSM4(ah[mf][0], ah[mf][1], ah[mf][2], ah[mf][3], base + o);
                LDSM4(al[mf][0], al[mf][1], al[mf][2], al[mf][3], base + 4096 + o);
            }
#pragma unroll
            for (int np = 0; np < 2; np++) {
                uint32_t o = SW64((uint32_t)((nbase + np * 16 + b_r) * 64 + ks * 32 + b_c));
                LDSM4(bh[np][0], bh[np][1], bh[np][2], bh[np][3], base + 8192 + o);
                LDSM4(bl[np][0], bl[np][1], bl[np][2], bl[np][3], base + 16384 + o);
            }
#pragma unroll
            for (int mf = 0; mf < 2; mf++)
#pragma unroll
                for (int nf = 0; nf < 4; nf++) {
                    int np = nf >> 1, oo = (nf & 1) * 2;
                    MMA(acc[mf][nf], ah[mf], bh[np][oo], bh[np][oo + 1]);
                    MMA(acc[mf][nf], ah[mf], bl[np][oo], bl[np][oo + 1]);
                    MMA(acc[mf][nf], al[mf], bh[np][oo], bh[np][oo + 1]);
                }
        }
        __syncthreads();
    }

    // Epilogue: c-frag (m16n8): c0,c1 at (lane>>2, (lane&3)*2), c2,c3 at row+8.
#pragma unroll
    for (int mf = 0; mf < 2; mf++) {
        int m0 = mbase + mf * 16 + (lane >> 2);
        int m1 = m0 + 8;
        int r0 = (m0 < mcnt) ? g_sorted[row0 + m0] : -1;
        int r1 = (m1 < mcnt) ? g_sorted[row0 + m1] : -1;
#pragma unroll
        for (int nf = 0; nf < 4; nf++) {
            int col = n0 + nbase + nf * 8 + (lane & 3) * 2;
            if (r0 >= 0)
                *(float2*)(out + (size_t)r0 * NOUT + col) =
                    make_float2(acc[mf][nf][0], acc[mf][nf][1]);
            if (r1 >= 0)
                *(float2*)(out + (size_t)r1 * NOUT + col) =
                    make_float2(acc[mf][nf][2], acc[mf][nf][3]);
        }
    }
}

extern "C" void kernel_launch(void* const* d_in, const int* in_sizes, int n_in,
                              void* d_out, int out_size) {
    const float* x = 0; const int* idx = 0; const float* w = 0;
    for (int i = 0; i < n_in; i++) {
        if (in_sizes[i] == BB)              idx = (const int*)d_in[i];
        else if (in_sizes[i] == BB * KIN)   x   = (const float*)d_in[i];
        else                                w   = (const float*)d_in[i];
    }
    k_setup<<<1, 1024>>>(idx);
    k_gemm<<<dim3(MAXT, 4), 256>>>(x, w, (float*)d_out);
}

// round 4
// speedup vs baseline: 2.6522x; 1.5139x over previous
#include <cuda_runtime.h>
#include <cuda_bf16.h>
#include <cstdint>

// SwitchingLinear: out[b,:] = W[idx[b]] @ x[b]
// B=2048, C=64, IN=OUT=512 fp32.
// ONE fused kernel: per-CTA ballot compaction of its expert's sample list,
// then split-bf16 HMMA grouped GEMM (v = hi+lo; D = Ah*Bh + Ah*Bl + Al*Bh).
// CTA = (expert, tile<2, N-block 128). K in 32-chunks, double-buffered
// 48KB static smem (compaction scratch overlaid, consumed to regs first).

#define BB    2048
#define CC    64
#define KIN   512
#define NOUT  512
#define TM    64
#define TN    128
#define KB    32
#define NCH   (KIN / KB)       // 16

__device__ __forceinline__ uint32_t smem_u32(const void* p) {
    uint32_t a;
    asm("{ .reg .u64 t; cvta.to.shared.u64 t, %1; cvt.u32.u64 %0, t; }"
        : "=r"(a) : "l"(p));
    return a;
}

#define SW64(o) ((o) ^ (((o) >> 3) & 0x30))

#define LDSM4(r0, r1, r2, r3, a)                                             \
    asm volatile("ldmatrix.sync.aligned.m8n8.x4.shared.b16 {%0,%1,%2,%3}, [%4];" \
                 : "=r"(r0), "=r"(r1), "=r"(r2), "=r"(r3) : "r"(a))

#define MMA(d, a, b0, b1)                                                    \
    asm volatile("mma.sync.aligned.m16n8k16.row.col.f32.bf16.bf16.f32 "      \
                 "{%0,%1,%2,%3},{%4,%5,%6,%7},{%8,%9},{%0,%1,%2,%3};"        \
                 : "+f"((d)[0]), "+f"((d)[1]), "+f"((d)[2]), "+f"((d)[3])    \
                 : "r"((a)[0]), "r"((a)[1]), "r"((a)[2]), "r"((a)[3]),       \
                   "r"(b0), "r"(b1))

// Split fp32 pair -> bf16x2 hi + bf16x2 lo (lo = v - float(hi)).
__device__ __forceinline__ void cvt2(float f0, float f1, uint32_t& h, uint32_t& l) {
    asm("cvt.rn.bf16x2.f32 %0, %1, %2;" : "=r"(h) : "f"(f1), "f"(f0));
    float h0 = __uint_as_float(h << 16);
    float h1 = __uint_as_float(h & 0xFFFF0000u);
    float l0 = f0 - h0, l1 = f1 - h1;
    asm("cvt.rn.bf16x2.f32 %0, %1, %2;" : "=r"(l) : "f"(l1), "f"(l0));
}

__global__ __launch_bounds__(256, 2)
void k_all(const float* __restrict__ x, const float* __restrict__ w,
           const int* __restrict__ idx, float* __restrict__ out) {
    __shared__ __align__(1024) char sm[49152];

    int t = threadIdx.x, wid = t >> 5, lane = t & 31;
    int e    = blockIdx.x & 63;
    int tile = blockIdx.x >> 6;
    int n0   = blockIdx.y * TN;

    // ---- phase 0: index dtype detect + ballot compaction (smem scratch) ----
    int* s_list = (int*)sm;          // [128]
    int* s_wcnt = (int*)(sm + 512);  // [8]
    int* s_flag = (int*)(sm + 552);

    if (t == 0) *s_flag = 0;
    __syncthreads();
    if (t < 128 && idx[2 * t + 1]) atomicOr(s_flag, 1);
    __syncthreads();
    const int is64 = (*s_flag == 0);

    uint32_t bal[8];
    int base = wid * 256;
    {
        int c_w = 0;
#pragma unroll
        for (int j = 0; j < 8; j++) {
            int smp = base + j * 32 + lane;
            int c = is64 ? idx[2 * smp] : idx[smp];
            bal[j] = __ballot_sync(0xffffffffu, c == e);
            c_w += __popc(bal[j]);
        }
        if (lane == 0) s_wcnt[wid] = c_w;
    }
    __syncthreads();
    int woff = 0, cnt = 0;
#pragma unroll
    for (int k = 0; k < 8; k++) {
        int v = s_wcnt[k];
        if (k < wid) woff += v;
        cnt += v;
    }
    if (tile * TM >= cnt) return;     // uniform across CTA

    {
        int run = woff;
#pragma unroll
        for (int j = 0; j < 8; j++) {
            int smp = base + j * 32 + lane;
            if ((bal[j] >> lane) & 1) {
                int pos = run + __popc(bal[j] & ((1u << lane) - 1));
                if (pos < 128) s_list[pos] = smp;
            }
            run += __popc(bal[j]);
        }
    }
    __syncthreads();

    int mcnt = cnt - tile * TM;
    if (mcnt > TM) mcnt = TM;
    const int* lst = s_list + tile * TM;

    // Pull everything this thread needs from s_list into registers,
    // then the stage buffers may overwrite it.
    int lrow = t >> 2;                    // loader row 0..63
    int asrc = (lrow < mcnt) ? lst[lrow] : -1;

    int mbase = (wid & 1) * 32;
    int nbase = (wid >> 1) * 32;
    int er0[2], er1[2];                   // epilogue row ids per m-frag
#pragma unroll
    for (int mf = 0; mf < 2; mf++) {
        int m0 = mbase + mf * 16 + (lane >> 2);
        int m1 = m0 + 8;
        er0[mf] = (m0 < mcnt) ? lst[m0] : -1;
        er1[mf] = (m1 < mcnt) ? lst[m1] : -1;
    }
    __syncthreads();                      // scratch now dead; stages own sm

    // ---- phase 1: grouped GEMM (R3 core) ----
    const uint32_t sb = smem_u32(sm);
    const float* wc = w + (size_t)e * (NOUT * KIN) + (size_t)n0 * KIN;

    int kf = (t & 3) * 8;                 // 0,8,16,24 within 32-chunk
    const float* ap  = x  + (size_t)(asrc < 0 ? 0 : asrc) * KIN + kf;
    const float* bp0 = wc + (size_t)lrow * KIN + kf;
    const float* bp1 = bp0 + (size_t)64 * KIN;

    float4 av[2], bv[4];
    if (asrc >= 0) { av[0] = *(const float4*)ap; av[1] = *(const float4*)(ap + 4); }
    else { av[0] = make_float4(0.f, 0.f, 0.f, 0.f); av[1] = av[0]; }
    bv[0] = *(const float4*)bp0; bv[1] = *(const float4*)(bp0 + 4);
    bv[2] = *(const float4*)bp1; bv[3] = *(const float4*)(bp1 + 4);

    int a_r = (lane & 7) + ((lane >> 3) & 1) * 8;
    int a_c = ((lane >> 4) & 1) * 16;
    int b_r = (lane & 7) + ((lane >> 4) & 1) * 8;
    int b_c = ((lane >> 3) & 1) * 16;

    float acc[2][4][4];
#pragma unroll
    for (int i = 0; i < 2; i++)
#pragma unroll
        for (int j = 0; j < 4; j++)
#pragma unroll
            for (int q = 0; q < 4; q++) acc[i][j][q] = 0.f;

    uint32_t sts  = SW64((uint32_t)(lrow * 64 + (t & 3) * 16));
    uint32_t sts2 = SW64((uint32_t)((lrow + 64) * 64 + (t & 3) * 16));

#pragma unroll 1
    for (int s = 0; s < NCH; s++) {
        char* stg = sm + (s & 1) * 24576;
        {
            uint32_t h0, l0, h1, l1, h2, l2, h3, l3;
            cvt2(av[0].x, av[0].y, h0, l0); cvt2(av[0].z, av[0].w, h1, l1);
            cvt2(av[1].x, av[1].y, h2, l2); cvt2(av[1].z, av[1].w, h3, l3);
            *(uint4*)(stg + sts)        = make_uint4(h0, h1, h2, h3);
            *(uint4*)(stg + 4096 + sts) = make_uint4(l0, l1, l2, l3);
            cvt2(bv[0].x, bv[0].y, h0, l0); cvt2(bv[0].z, bv[0].w, h1, l1);
            cvt2(bv[1].x, bv[1].y, h2, l2); cvt2(bv[1].z, bv[1].w, h3, l3);
            *(uint4*)(stg + 8192 + sts)  = make_uint4(h0, h1, h2, h3);
            *(uint4*)(stg + 16384 + sts) = make_uint4(l0, l1, l2, l3);
            cvt2(bv[2].x, bv[2].y, h0, l0); cvt2(bv[2].z, bv[2].w, h1, l1);
            cvt2(bv[3].x, bv[3].y, h2, l2); cvt2(bv[3].z, bv[3].w, h3, l3);
            *(uint4*)(stg + 8192 + sts2)  = make_uint4(h0, h1, h2, h3);
            *(uint4*)(stg + 16384 + sts2) = make_uint4(l0, l1, l2, l3);
        }
        __syncthreads();

        if (s + 1 < NCH) {
            int g = (s + 1) * KB;
            if (asrc >= 0) {
                av[0] = *(const float4*)(ap + g);
                av[1] = *(const float4*)(ap + g + 4);
            }
            bv[0] = *(const float4*)(bp0 + g); bv[1] = *(const float4*)(bp0 + g + 4);
            bv[2] = *(const float4*)(bp1 + g); bv[3] = *(const float4*)(bp1 + g + 4);
        }

        uint32_t bbase = sb + (uint32_t)((s & 1) * 24576);
#pragma unroll
        for (int ks = 0; ks < 2; ks++) {
            uint32_t ah[2][4], al[2][4], bh[2][4], bl[2][4];
#pragma unroll
            for (int mf = 0; mf < 2; mf++) {
                uint32_t o = SW64((uint32_t)((mbase + mf * 16 + a_r) * 64 + ks * 32 + a_c));
                LDSM4(ah[mf][0], ah[mf][1], ah[mf][2], ah[mf][3], bbase + o);
                LDSM4(al[mf][0], al[mf][1], al[mf][2], al[mf][3], bbase + 4096 + o);
            }
#pragma unroll
            for (int np = 0; np < 2; np++) {
                uint32_t o = SW64((uint32_t)((nbase + np * 16 + b_r) * 64 + ks * 32 + b_c));
                LDSM4(bh[np][0], bh[np][1], bh[np][2], bh[np][3], bbase + 8192 + o);
                LDSM4(bl[np][0], bl[np][1], bl[np][2], bl[np][3], bbase + 16384 + o);
            }
#pragma unroll
            for (int mf = 0; mf < 2; mf++)
#pragma unroll
                for (int nf = 0; nf < 4; nf++) {
                    int np = nf >> 1, oo = (nf & 1) * 2;
                    MMA(acc[mf][nf], ah[mf], bh[np][oo], bh[np][oo + 1]);
                    MMA(acc[mf][nf], ah[mf], bl[np][oo], bl[np][oo + 1]);
                    MMA(acc[mf][nf], al[mf], bh[np][oo], bh[np][oo + 1]);
                }
        }
        __syncthreads();
    }

    // ---- epilogue ----
#pragma unroll
    for (int mf = 0; mf < 2; mf++) {
#pragma unroll
        for (int nf = 0; nf < 4; nf++) {
            int col = n0 + nbase + nf * 8 + (lane & 3) * 2;
            if (er0[mf] >= 0)
                *(float2*)(out + (size_t)er0[mf] * NOUT + col) =
                    make_float2(acc[mf][nf][0], acc[mf][nf][1]);
            if (er1[mf] >= 0)
                *(float2*)(out + (size_t)er1[mf] * NOUT + col) =
                    make_float2(acc[mf][nf][2], acc[mf][nf][3]);
        }
    }
}

extern "C" void kernel_launch(void* const* d_in, const int* in_sizes, int n_in,
                              void* d_out, int out_size) {
    const float* x = 0; const int* idx = 0; const float* w = 0;
    for (int i = 0; i < n_in; i++) {
        if (in_sizes[i] == BB)              idx = (const int*)d_in[i];
        else if (in_sizes[i] == BB * KIN)   x   = (const float*)d_in[i];
        else                                w   = (const float*)d_in[i];
    }
    k_all<<<dim3(2 * CC, NOUT / TN), 256>>>(x, w, idx, (float*)d_out);
}